// round 6
// baseline (speedup 1.0000x reference)
#include <cuda_runtime.h>
#include <math.h>

#define BB 32
#define NN 384
#define RR 16
#define THREADS 384
#define ROWS_PER_BLOCK 16
#define ROW_CHUNKS (NN / ROWS_PER_BLOCK)          // 24
#define ORDER_BLOCKS (BB * ROW_CHUNKS)            // 768
#define REL_BLOCKS ((BB * NN) / THREADS)          // 32
#define GRID (ORDER_BLOCKS + REL_BLOCKS)          // 800
#define NWARPS (THREADS / 32)                     // 12

// Scratch (no alloc allowed) — per-block partials + completion counter.
__device__ double g_osum[ORDER_BLOCKS];
__device__ double g_ocnt[ORDER_BLOCKS];
__device__ double g_rsum[REL_BLOCKS];
__device__ double g_rcnt[REL_BLOCKS];
__device__ unsigned int g_done = 0;

__global__ __launch_bounds__(THREADS, 3)
void fused_kernel(const float* __restrict__ logits,
                  const float* __restrict__ rl,
                  const int* __restrict__ ro,
                  const int* __restrict__ parent,
                  const int* __restrict__ relation,
                  const int* __restrict__ mask,
                  float* __restrict__ out, int out_size) {
    __shared__ int ro_s[NN];
    __shared__ int m_s[NN];
    __shared__ double ws[NWARPS];
    __shared__ double wc[NWARPS];
    __shared__ double ws2[NWARPS];
    __shared__ double wc2[NWARPS];
    __shared__ bool is_last;

    const int t    = threadIdx.x;
    const int warp = t >> 5;
    const int lane = t & 31;

    double blk_s = 0.0, blk_c = 0.0;

    if (blockIdx.x < ORDER_BLOCKS) {
        // ---------------- order BCE part ----------------
        const int b  = blockIdx.x / ROW_CHUNKS;
        const int i0 = (blockIdx.x % ROW_CHUNKS) * ROWS_PER_BLOCK;

        const int tx = t % 96;        // float4 column group: j = 4*tx + k
        const int ty = t / 96;        // 0..3, row sub-offset (rows i0+ty+4r)
        const int j0 = 4 * tx;

        // Small per-thread scalar loads first (gate the barrier).
        const int ro_me = ro[b * NN + t];
        const int m_me  = mask[b * NN + t];

        const float4* base =
            (const float4*)(logits + ((size_t)b * NN + i0) * NN) + tx;

        // 4 independent streamed LDG.128 — latency overlaps smem fill + barrier.
        const float4 a0 = __ldcs(base + (size_t)(ty +  0) * 96);
        const float4 a1 = __ldcs(base + (size_t)(ty +  4) * 96);
        const float4 a2 = __ldcs(base + (size_t)(ty +  8) * 96);
        const float4 a3 = __ldcs(base + (size_t)(ty + 12) * 96);

        ro_s[t] = ro_me;
        m_s[t]  = m_me;
        __syncthreads();

        int   roj[4];
        float mjf[4];
        #pragma unroll
        for (int k = 0; k < 4; k++) {
            roj[k] = ro_s[j0 + k];
            mjf[k] = (m_s[j0 + k] != 0) ? 1.0f : 0.0f;
        }

        float fsum = 0.0f;
        float fcnt = 0.0f;

        const float4 av[4] = {a0, a1, a2, a3};
        #pragma unroll
        for (int r = 0; r < 4; r++) {
            const int i = i0 + ty + 4 * r;
            const float mif = (m_s[i] != 0) ? 1.0f : 0.0f;
            const int   roi = ro_s[i];
            const float xv[4] = {av[r].x, av[r].y, av[r].z, av[r].w};
            #pragma unroll
            for (int k = 0; k < 4; k++) {
                const int j = j0 + k;
                float vm = mif * mjf[k];
                vm = (i == j) ? 0.0f : vm;
                const float x  = xv[k];
                // softplus(x) - x*t == softplus(t ? -x : x)
                const float y  = (roi < roj[k]) ? -x : x;
                const float ax = fabsf(x);
                const float l  = __logf(1.0f + __expf(-ax));
                const float bce = fmaxf(y, 0.0f) + l;
                fsum = fmaf(vm, bce, fsum);
                fcnt += vm;
            }
        }
        blk_s = (double)fsum;
        blk_c = (double)fcnt;
    } else {
        // ---------------- relation CE part ----------------
        const int idx = (blockIdx.x - ORDER_BLOCKS) * THREADS + t;
        const int b = idx / NN;
        const int i = idx - b * NN;
        const int p = parent[idx];
        int       r = relation[idx];
        float ce = 0.0f;
        int   v  = 0;
        if (mask[idx] != 0 && p >= 0 && p < NN && r >= 0) {
            r = min(r, RR - 1);
            const float4* row =
                (const float4*)(rl + (((size_t)b * NN + p) * NN + i) * RR);
            float4 v0 = __ldg(row + 0);
            float4 v1 = __ldg(row + 1);
            float4 v2 = __ldg(row + 2);
            float4 v3 = __ldg(row + 3);
            float vals[RR] = {v0.x,v0.y,v0.z,v0.w, v1.x,v1.y,v1.z,v1.w,
                              v2.x,v2.y,v2.z,v2.w, v3.x,v3.y,v3.z,v3.w};
            float m = vals[0];
            #pragma unroll
            for (int k = 1; k < RR; k++) m = fmaxf(m, vals[k]);
            float ssum = 0.0f;
            #pragma unroll
            for (int k = 0; k < RR; k++) ssum += __expf(vals[k] - m);
            ce = m + __logf(ssum) - vals[r];
            v = 1;
        }
        blk_s = (double)ce;
        blk_c = (double)v;
        __syncthreads();   // keep barrier count symmetric with order path
    }

    // ---------------- block reduction (both paths) ----------------
    #pragma unroll
    for (int off = 16; off > 0; off >>= 1) {
        blk_s += __shfl_down_sync(0xffffffffu, blk_s, off);
        blk_c += __shfl_down_sync(0xffffffffu, blk_c, off);
    }
    if (lane == 0) { ws[warp] = blk_s; wc[warp] = blk_c; }
    __syncthreads();
    if (t == 0) {
        double S = 0.0, C = 0.0;
        #pragma unroll
        for (int w = 0; w < NWARPS; w++) { S += ws[w]; C += wc[w]; }
        if (blockIdx.x < ORDER_BLOCKS) {
            g_osum[blockIdx.x] = S;
            g_ocnt[blockIdx.x] = C;
        } else {
            g_rsum[blockIdx.x - ORDER_BLOCKS] = S;
            g_rcnt[blockIdx.x - ORDER_BLOCKS] = C;
        }
    }

    // ---------------- last-block finalize ----------------
    __threadfence();
    if (t == 0) {
        is_last = (atomicAdd(&g_done, 1u) == (unsigned)(GRID - 1));
    }
    __syncthreads();
    if (!is_last) return;

    double os = 0.0, oc = 0.0, rs = 0.0, rc = 0.0;
    for (int k = t; k < ORDER_BLOCKS; k += THREADS) {
        os += __ldcg(&g_osum[k]);
        oc += __ldcg(&g_ocnt[k]);
    }
    if (t < REL_BLOCKS) {
        rs = __ldcg(&g_rsum[t]);
        rc = __ldcg(&g_rcnt[t]);
    }
    #pragma unroll
    for (int off = 16; off > 0; off >>= 1) {
        os += __shfl_down_sync(0xffffffffu, os, off);
        oc += __shfl_down_sync(0xffffffffu, oc, off);
        rs += __shfl_down_sync(0xffffffffu, rs, off);
        rc += __shfl_down_sync(0xffffffffu, rc, off);
    }
    if (lane == 0) { ws[warp] = os; wc[warp] = oc; ws2[warp] = rs; wc2[warp] = rc; }
    __syncthreads();
    if (t == 0) {
        double OS = 0.0, OC = 0.0, RS = 0.0, RC = 0.0;
        #pragma unroll
        for (int w = 0; w < NWARPS; w++) {
            OS += ws[w]; OC += wc[w]; RS += ws2[w]; RC += wc2[w];
        }
        const double order_loss = OS / fmax(OC, 1.0);
        const double rel_loss   = RS / fmax(RC, 1.0);
        const double total = order_loss + 0.5 * rel_loss;
        out[0] = (float)total;
        if (out_size > 1) out[1] = (float)order_loss;
        if (out_size > 2) out[2] = (float)rel_loss;
        g_done = 0;   // reset for next graph replay
    }
}

extern "C" void kernel_launch(void* const* d_in, const int* in_sizes, int n_in,
                              void* d_out, int out_size) {
    const float* order_logits    = (const float*)d_in[0];
    const float* relation_logits = (const float*)d_in[1];
    const int*   reading_orders  = (const int*)d_in[2];
    const int*   parent_ids      = (const int*)d_in[3];
    const int*   relations       = (const int*)d_in[4];
    const int*   region_mask     = (const int*)d_in[5];
    float* out = (float*)d_out;

    fused_kernel<<<GRID, THREADS>>>(order_logits, relation_logits,
                                    reading_orders, parent_ids, relations,
                                    region_mask, out, out_size);
}

// round 7
// speedup vs baseline: 1.2314x; 1.2314x over previous
#include <cuda_runtime.h>
#include <math.h>

#define BB 32
#define NN 384
#define RR 16
#define THREADS 384
#define ROWS_PER_BLOCK 32
#define ROW_CHUNKS (NN / ROWS_PER_BLOCK)          // 12
#define ORDER_BLOCKS (BB * ROW_CHUNKS)            // 384
#define REL_BLOCKS ((BB * NN) / THREADS)          // 32
#define GRID (ORDER_BLOCKS + REL_BLOCKS)          // 416
#define NWARPS (THREADS / 32)                     // 12
#define HUGE_RO 0x3fffffff
#define LN2F 0.69314718055994531f

// Scratch (no alloc allowed) — per-block partials + completion counter.
__device__ double g_osum[ORDER_BLOCKS];
__device__ double g_ocnt[ORDER_BLOCKS];
__device__ double g_rsum[REL_BLOCKS];
__device__ double g_rcnt[REL_BLOCKS];
__device__ unsigned int g_done = 0;

__global__ __launch_bounds__(THREADS)
void fused_kernel(const float* __restrict__ logits,
                  const float* __restrict__ rl,
                  const int* __restrict__ ro,
                  const int* __restrict__ parent,
                  const int* __restrict__ relation,
                  const int* __restrict__ mask,
                  float* __restrict__ out, int out_size) {
    __shared__ int s_s[NN];           // packed: mask ? ro : HUGE_RO
    __shared__ double ws[NWARPS];
    __shared__ double wc[NWARPS];
    __shared__ double ws2[NWARPS];
    __shared__ double wc2[NWARPS];
    __shared__ bool is_last;

    const int t    = threadIdx.x;
    const int warp = t >> 5;
    const int lane = t & 31;

    double blk_s = 0.0, blk_c = 0.0;

    if (blockIdx.x >= REL_BLOCKS) {
        // ---------------- order BCE part (R2-proven structure) ----------------
        const int ob = blockIdx.x - REL_BLOCKS;
        const int b  = ob / ROW_CHUNKS;
        const int i0 = (ob % ROW_CHUNKS) * ROWS_PER_BLOCK;
        const int j  = t;

        const int m_me  = mask[b * NN + j];
        const int ro_me = ro[b * NN + j];
        s_s[j] = m_me ? ro_me : HUGE_RO;
        __syncthreads();

        const int  sj = s_s[j];
        const bool pj = (sj < HUGE_RO);

        const float* base = logits + ((size_t)b * NN + i0) * NN + j;

        float fsum_y = 0.0f;   // sum of max(y,0)
        float fsum_l = 0.0f;   // sum of log2(1+exp(-|x|))
        int   cnt    = 0;

        #pragma unroll 8
        for (int ii = 0; ii < ROWS_PER_BLOCK; ii++) {
            const float x  = __ldg(base + (size_t)ii * NN);
            const int   si = s_s[i0 + ii];
            const bool valid = pj && (si < HUGE_RO);
            // target t = (ro_i < ro_j); bce = softplus(t ? -x : x)
            const float y  = (si < sj) ? -x : x;
            const float ax = fabsf(x);
            const float e  = __expf(-ax);             // FMUL + MUFU.EX2
            const float lg = __log2f(1.0f + e);       // FADD + MUFU.LG2
            const float my = fmaxf(y, 0.0f);
            if (valid) { fsum_y += my; fsum_l += lg; cnt++; }
        }

        // Remove the diagonal element (i == j) if it fell in this row chunk.
        if (pj && j >= i0 && j < i0 + ROWS_PER_BLOCK) {
            const float x  = __ldg(logits + (((size_t)b * NN + j) * NN + j));
            const float ax = fabsf(x);
            const float e  = __expf(-ax);
            const float lg = __log2f(1.0f + e);
            const float my = fmaxf(x, 0.0f);          // si==sj -> y = x
            fsum_y -= my; fsum_l -= lg; cnt--;
        }

        blk_s = (double)(fsum_y + LN2F * fsum_l);
        blk_c = (double)cnt;
    } else {
        // ---------------- relation CE part ----------------
        const int idx = blockIdx.x * THREADS + t;
        const int b = idx / NN;
        const int i = idx - b * NN;
        const int p = parent[idx];
        int       r = relation[idx];
        float ce = 0.0f;
        int   v  = 0;
        if (mask[idx] != 0 && p >= 0 && p < NN && r >= 0) {
            r = min(r, RR - 1);
            const float4* row =
                (const float4*)(rl + (((size_t)b * NN + p) * NN + i) * RR);
            float4 v0 = __ldg(row + 0);
            float4 v1 = __ldg(row + 1);
            float4 v2 = __ldg(row + 2);
            float4 v3 = __ldg(row + 3);
            float vals[RR] = {v0.x,v0.y,v0.z,v0.w, v1.x,v1.y,v1.z,v1.w,
                              v2.x,v2.y,v2.z,v2.w, v3.x,v3.y,v3.z,v3.w};
            float m = vals[0];
            #pragma unroll
            for (int k = 1; k < RR; k++) m = fmaxf(m, vals[k]);
            float ssum = 0.0f;
            #pragma unroll
            for (int k = 0; k < RR; k++) ssum += __expf(vals[k] - m);
            ce = m + __logf(ssum) - vals[r];
            v = 1;
        }
        blk_s = (double)ce;
        blk_c = (double)v;
    }

    // ---------------- block reduction (both paths) ----------------
    #pragma unroll
    for (int off = 16; off > 0; off >>= 1) {
        blk_s += __shfl_down_sync(0xffffffffu, blk_s, off);
        blk_c += __shfl_down_sync(0xffffffffu, blk_c, off);
    }
    if (lane == 0) { ws[warp] = blk_s; wc[warp] = blk_c; }
    __syncthreads();
    if (t == 0) {
        double S = 0.0, C = 0.0;
        #pragma unroll
        for (int w = 0; w < NWARPS; w++) { S += ws[w]; C += wc[w]; }
        if (blockIdx.x >= REL_BLOCKS) {
            g_osum[blockIdx.x - REL_BLOCKS] = S;
            g_ocnt[blockIdx.x - REL_BLOCKS] = C;
        } else {
            g_rsum[blockIdx.x] = S;
            g_rcnt[blockIdx.x] = C;
        }
    }

    // ---------------- last-block finalize ----------------
    __threadfence();
    if (t == 0) {
        is_last = (atomicAdd(&g_done, 1u) == (unsigned)(GRID - 1));
    }
    __syncthreads();
    if (!is_last) return;

    double os = 0.0, oc = 0.0, rs = 0.0, rc = 0.0;
    for (int k = t; k < ORDER_BLOCKS; k += THREADS) {
        os += __ldcg(&g_osum[k]);
        oc += __ldcg(&g_ocnt[k]);
    }
    if (t < REL_BLOCKS) {
        rs = __ldcg(&g_rsum[t]);
        rc = __ldcg(&g_rcnt[t]);
    }
    #pragma unroll
    for (int off = 16; off > 0; off >>= 1) {
        os += __shfl_down_sync(0xffffffffu, os, off);
        oc += __shfl_down_sync(0xffffffffu, oc, off);
        rs += __shfl_down_sync(0xffffffffu, rs, off);
        rc += __shfl_down_sync(0xffffffffu, rc, off);
    }
    if (lane == 0) { ws[warp] = os; wc[warp] = oc; ws2[warp] = rs; wc2[warp] = rc; }
    __syncthreads();
    if (t == 0) {
        double OS = 0.0, OC = 0.0, RS = 0.0, RC = 0.0;
        #pragma unroll
        for (int w = 0; w < NWARPS; w++) {
            OS += ws[w]; OC += wc[w]; RS += ws2[w]; RC += wc2[w];
        }
        const double order_loss = OS / fmax(OC, 1.0);
        const double rel_loss   = RS / fmax(RC, 1.0);
        const double total = order_loss + 0.5 * rel_loss;
        out[0] = (float)total;
        if (out_size > 1) out[1] = (float)order_loss;
        if (out_size > 2) out[2] = (float)rel_loss;
        g_done = 0;   // reset for next graph replay
    }
}

extern "C" void kernel_launch(void* const* d_in, const int* in_sizes, int n_in,
                              void* d_out, int out_size) {
    const float* order_logits    = (const float*)d_in[0];
    const float* relation_logits = (const float*)d_in[1];
    const int*   reading_orders  = (const int*)d_in[2];
    const int*   parent_ids      = (const int*)d_in[3];
    const int*   relations       = (const int*)d_in[4];
    const int*   region_mask     = (const int*)d_in[5];
    float* out = (float*)d_out;

    fused_kernel<<<GRID, THREADS>>>(order_logits, relation_logits,
                                    reading_orders, parent_ids, relations,
                                    region_mask, out, out_size);
}